// round 1
// baseline (speedup 1.0000x reference)
#include <cuda_runtime.h>

// ---------------------------------------------------------------------------
// NeuralODE Tsit5 — persistent fused kernel.
// Each CTA: 16 batch rows, all weights in SMEM, full 49-step integration.
// f32x2 packed FMA (FFMA2) over the K dimension, horizontal add at the end.
// ---------------------------------------------------------------------------

#define NTHREADS 128
#define M_TILE   16

// Tsit5 tableau
__constant__ float d_cs[6] = {0.0f, 0.161f, 0.327f, 0.9f, 0.9800255409045097f, 1.0f};
__constant__ float d_A[6][5] = {
    {0.f, 0.f, 0.f, 0.f, 0.f},
    {0.161f, 0.f, 0.f, 0.f, 0.f},
    {-0.008480655492356989f, 0.335480655492357f, 0.f, 0.f, 0.f},
    {2.8971530571054935f, -6.359448489975075f, 4.3622954328695815f, 0.f, 0.f},
    {5.325864828439257f, -11.748883564062828f, 7.4955393428898365f, -0.09249506636175525f, 0.f},
    {5.86145544294642f, -12.92096931784711f, 8.159367898576159f, -0.071584973281401f, -0.028269050394068383f}
};
__constant__ float d_B[6] = {
    0.09646076681806523f, 0.01f, 0.4798896504144996f,
    1.379008574103742f, -3.290069515436081f, 2.324710524099774f
};

// ---- f32x2 helpers ---------------------------------------------------------
__device__ __forceinline__ unsigned long long pack2(float x, float y) {
    unsigned long long r;
    asm("mov.b64 %0, {%1, %2};" : "=l"(r) : "f"(x), "f"(y));
    return r;
}
__device__ __forceinline__ float2 unpack2(unsigned long long v) {
    float2 f;
    asm("mov.b64 {%0, %1}, %2;" : "=f"(f.x), "=f"(f.y) : "l"(v));
    return f;
}
__device__ __forceinline__ void ffma2(unsigned long long& d,
                                      unsigned long long a,
                                      unsigned long long b) {
    asm("fma.rn.f32x2 %0, %1, %2, %0;" : "+l"(d) : "l"(a), "l"(b));
}

// ---- SMEM layout (bytes) ---------------------------------------------------
// wp0: 36*128 u64  (layer0 weights, K padded 65->72, k-pair packed, transposed)
// wp1: 64*128 u64
// wp2: 64*64  u64
// b0[128], b1[128], b2[64]
// act0[16][72], act1[16][128], act2[16][128]
// kbuf[6][16][64], y[16][64]
#define KP0 36
#define KP1 64
#define KP2 64
#define S_ACT0 72

#define U64_WORDS (KP0*128 + KP1*128 + KP2*64)
#define F32_WORDS (128 + 128 + 64 + 16*S_ACT0 + 16*128 + 16*128 + 6*16*64 + 16*64)
#define SMEM_BYTES (U64_WORDS*8 + F32_WORDS*4)

// ---- one MLP layer: out[16][N] = act[16][K] @ W^T + b ----------------------
// Warp tiling: warp = (rowhalf, colhalf). Thread: 8 rows x (N/64) col-groups.
template<int N, int KP, int SIN, bool RELU>
__device__ __noinline__ void mlp_layer(const float* __restrict__ actIn,
                                       const unsigned long long* __restrict__ wp,
                                       const float* __restrict__ bias,
                                       float* __restrict__ actOut,
                                       int strideOut) {
    constexpr int NC = N / 64;           // col-groups per thread (2 or 1)
    const int tid  = threadIdx.x;
    const int lane = tid & 31;
    const int warp = tid >> 5;
    const int rbase = (warp & 1) * 8;
    const int cbase = (warp >> 1) * (N / 2);

    unsigned long long acc[8][NC];
#pragma unroll
    for (int r = 0; r < 8; r++)
#pragma unroll
        for (int c = 0; c < NC; c++) acc[r][c] = 0ull;

    const float* aIn = actIn + rbase * SIN;

#pragma unroll 2
    for (int i = 0; i < KP; i += 2) {
        ulonglong2 in[8];
#pragma unroll
        for (int r = 0; r < 8; r++)
            in[r] = *reinterpret_cast<const ulonglong2*>(aIn + r * SIN + 2 * i);
#pragma unroll
        for (int c = 0; c < NC; c++) {
            const int n = cbase + lane + 32 * c;
            const unsigned long long wA = wp[i * N + n];
            const unsigned long long wB = wp[(i + 1) * N + n];
#pragma unroll
            for (int r = 0; r < 8; r++) {
                ffma2(acc[r][c], in[r].x, wA);
                ffma2(acc[r][c], in[r].y, wB);
            }
        }
    }

#pragma unroll
    for (int c = 0; c < NC; c++) {
        const int n = cbase + lane + 32 * c;
        const float bv = bias[n];
#pragma unroll
        for (int r = 0; r < 8; r++) {
            float2 p = unpack2(acc[r][c]);
            float v = p.x + p.y + bv;
            if (RELU) v = fmaxf(v, 0.0f);
            actOut[(rbase + r) * strideOut + n] = v;
        }
    }
}

// ---------------------------------------------------------------------------
__global__ void __launch_bounds__(NTHREADS, 1)
node_kernel(const float* __restrict__ y0, const float* __restrict__ ts,
            const float* __restrict__ w0, const float* __restrict__ b0,
            const float* __restrict__ w1, const float* __restrict__ b1,
            const float* __restrict__ w2, const float* __restrict__ b2,
            float* __restrict__ out, int T) {
    extern __shared__ unsigned long long smem_u64[];
    unsigned long long* wp0 = smem_u64;
    unsigned long long* wp1 = wp0 + KP0 * 128;
    unsigned long long* wp2 = wp1 + KP1 * 128;
    float* fb   = reinterpret_cast<float*>(wp2 + KP2 * 64);
    float* sb0  = fb;            fb += 128;
    float* sb1  = fb;            fb += 128;
    float* sb2  = fb;            fb += 64;
    float* act0 = fb;            fb += 16 * S_ACT0;
    float* act1 = fb;            fb += 16 * 128;
    float* act2 = fb;            fb += 16 * 128;
    float* kbuf = fb;            fb += 6 * 16 * 64;
    float* ysh  = fb;

    const int tid  = threadIdx.x;
    const int row0 = blockIdx.x * M_TILE;

    // ---- one-time setup: weights (transposed + k-pair packed), biases, y ----
    for (int idx = tid; idx < KP0 * 128; idx += NTHREADS) {
        int kp = idx >> 7, n = idx & 127;
        int k0 = 2 * kp, k1 = 2 * kp + 1;
        float a = (k0 < 65) ? w0[n * 65 + k0] : 0.0f;
        float b = (k1 < 65) ? w0[n * 65 + k1] : 0.0f;
        wp0[idx] = pack2(a, b);
    }
    for (int idx = tid; idx < KP1 * 128; idx += NTHREADS) {
        int kp = idx >> 7, n = idx & 127;
        wp1[idx] = pack2(w1[n * 128 + 2 * kp], w1[n * 128 + 2 * kp + 1]);
    }
    for (int idx = tid; idx < KP2 * 64; idx += NTHREADS) {
        int kp = idx >> 6, n = idx & 63;
        wp2[idx] = pack2(w2[n * 128 + 2 * kp], w2[n * 128 + 2 * kp + 1]);
    }
    for (int idx = tid; idx < 128; idx += NTHREADS) { sb0[idx] = b0[idx]; sb1[idx] = b1[idx]; }
    for (int idx = tid; idx < 64;  idx += NTHREADS) sb2[idx] = b2[idx];
    for (int idx = tid; idx < M_TILE * 64; idx += NTHREADS)
        ysh[idx] = y0[row0 * 64 + idx];
    // zero K-pad columns of act0 (written once, never touched again)
    if (tid < M_TILE) {
#pragma unroll
        for (int kk = 65; kk < S_ACT0; kk++) act0[tid * S_ACT0 + kk] = 0.0f;
    }
    __syncthreads();

    const float dt = ts[1] - ts[0];
    const int steps = T - 1;

    for (int st = 0; st < steps; st++) {
        const float t = ts[st];
        for (int s = 0; s < 6; s++) {
            // ---- stage prologue: act0 = [t_s, y + dt * sum_j A[s][j] k_j] ----
            if (tid < M_TILE) act0[tid * S_ACT0] = fmaf(d_cs[s], dt, t);
#pragma unroll
            for (int i = 0; i < 8; i++) {
                const int e = tid + i * NTHREADS;
                float acc = 0.0f;
                for (int j = 0; j < s; j++)
                    acc = fmaf(d_A[s][j], kbuf[j * 1024 + e], acc);
                act0[(e >> 6) * S_ACT0 + 1 + (e & 63)] = fmaf(dt, acc, ysh[e]);
            }
            __syncthreads();
            mlp_layer<128, KP0, S_ACT0, true >(act0, wp0, sb0, act1, 128);
            __syncthreads();
            mlp_layer<128, KP1, 128,    true >(act1, wp1, sb1, act2, 128);
            __syncthreads();
            mlp_layer<64,  KP2, 128,    false>(act2, wp2, sb2, kbuf + s * 1024, 64);
            __syncthreads();
        }
        // ---- y += dt * sum_j B[j] k_j ----
#pragma unroll
        for (int i = 0; i < 8; i++) {
            const int e = tid + i * NTHREADS;
            float acc = d_B[0] * kbuf[e];
#pragma unroll
            for (int j = 1; j < 6; j++)
                acc = fmaf(d_B[j], kbuf[j * 1024 + e], acc);
            ysh[e] = fmaf(dt, acc, ysh[e]);
        }
        __syncthreads();
    }

    for (int idx = tid; idx < M_TILE * 64; idx += NTHREADS)
        out[row0 * 64 + idx] = ysh[idx];
}

// ---------------------------------------------------------------------------
extern "C" void kernel_launch(void* const* d_in, const int* in_sizes, int n_in,
                              void* d_out, int out_size) {
    const float* y0 = (const float*)d_in[0];
    const float* ts = (const float*)d_in[1];
    const float* w0 = (const float*)d_in[2];
    const float* b0 = (const float*)d_in[3];
    const float* w1 = (const float*)d_in[4];
    const float* b1 = (const float*)d_in[5];
    const float* w2 = (const float*)d_in[6];
    const float* b2 = (const float*)d_in[7];

    const int B = in_sizes[0] / 64;   // batch rows
    const int T = in_sizes[1];        // number of time points

    cudaFuncSetAttribute(node_kernel,
                         cudaFuncAttributeMaxDynamicSharedMemorySize, SMEM_BYTES);

    node_kernel<<<B / M_TILE, NTHREADS, SMEM_BYTES>>>(
        y0, ts, w0, b0, w1, b1, w2, b2, (float*)d_out, T);
}